// round 5
// baseline (speedup 1.0000x reference)
#include <cuda_runtime.h>
#include <math.h>
#include <stdint.h>

#define B_SZ   2
#define T_SEQ  2048
#define C_EMB  1024
#define NHEAD  16
#define H_DIM  64
#define M_TOT  (B_SZ * T_SEQ)   // 4096

// Scratch (static device arrays)
__device__ float g_qkv[(size_t)M_TOT * 3 * C_EMB];           // [B,T,3C] fp32
__device__ float g_xh[(size_t)M_TOT * C_EMB];
__device__ float g_xl[(size_t)M_TOT * C_EMB];
__device__ float g_wqh[(size_t)3 * C_EMB * C_EMB];
__device__ float g_wql[(size_t)3 * C_EMB * C_EMB];
__device__ float g_wph[(size_t)C_EMB * C_EMB];
__device__ float g_wpl[(size_t)C_EMB * C_EMB];
__device__ float g_q[(size_t)B_SZ * NHEAD * T_SEQ * H_DIM];  // tf32 pattern, pre-scaled
__device__ float g_k[(size_t)B_SZ * NHEAD * T_SEQ * H_DIM];  // tf32 pattern
__device__ float g_v[(size_t)B_SZ * NHEAD * T_SEQ * H_DIM];  // tf32 pattern
__device__ float g_yh[(size_t)M_TOT * C_EMB];
__device__ float g_yl[(size_t)M_TOT * C_EMB];
__device__ float g_cos[T_SEQ * H_DIM];
__device__ float g_sin[T_SEQ * H_DIM];

// ---------------------------------------------------------------------------
__device__ __forceinline__ uint32_t f2tf(float x) {
    uint32_t r;
    asm("cvt.rna.tf32.f32 %0, %1;" : "=r"(r) : "f"(x));
    return r;
}
__device__ __forceinline__ void mma_tf32(float* c,
                                         uint32_t a0, uint32_t a1, uint32_t a2, uint32_t a3,
                                         uint32_t b0, uint32_t b1) {
    asm volatile(
        "mma.sync.aligned.m16n8k8.row.col.f32.tf32.tf32.f32 "
        "{%0,%1,%2,%3}, {%4,%5,%6,%7}, {%8,%9}, {%0,%1,%2,%3};"
        : "+f"(c[0]), "+f"(c[1]), "+f"(c[2]), "+f"(c[3])
        : "r"(a0), "r"(a1), "r"(a2), "r"(a3), "r"(b0), "r"(b1));
}
__device__ __forceinline__ void cp16(uint32_t saddr, const void* g) {
    asm volatile("cp.async.cg.shared.global [%0], [%1], 16;" :: "r"(saddr), "l"(g));
}

// ---------------------------------------------------------------------------
// hi/lo tf32 split (elementwise)
// ---------------------------------------------------------------------------
__global__ void split_kernel(const float* __restrict__ src,
                             float* __restrict__ h, float* __restrict__ l, int n) {
    int i = blockIdx.x * blockDim.x + threadIdx.x;
    if (i >= n) return;
    float v = src[i];
    float hv = __uint_as_float(f2tf(v));
    h[i] = hv;
    l[i] = __uint_as_float(f2tf(v - hv));
}

// ---------------------------------------------------------------------------
// RoPE table
// ---------------------------------------------------------------------------
__global__ void rope_table_kernel() {
    int i = blockIdx.x * blockDim.x + threadIdx.x;
    if (i >= T_SEQ * H_DIM) return;
    int t = i >> 6;
    int d = i & 63;
    double f = pow(10000.0, -(double)(d & 31) / 32.0);
    double ang = (double)t * f;
    g_cos[i] = (float)cos(ang);
    g_sin[i] = (float)sin(ang);
}

// ---------------------------------------------------------------------------
// SGEMM, pre-split inputs: C[M,N] = (Ah+Al)[M,K] * (Bh+Bl)[N,K]^T  (3-pass)
// 128x128 tile, BK=16, 256 threads, warp tile 32x64, cp.async 2-stage.
// ---------------------------------------------------------------------------
#define ALD 20
#define TILE_F (128 * ALD)          // 2560
#define STAGE_F (4 * TILE_F)        // 10240
#define GEMM_SMEM_BYTES (2 * STAGE_F * 4)  // 81920

__device__ __forceinline__ void gemm_load_stage(
    float* sm, int s, const float* Ah, const float* Al,
    const float* Bh, const float* Bl, int K, int bm, int bn, int k0, int t) {
    float* base = sm + s * STAGE_F;
    int c0 = t * 2;
#pragma unroll
    for (int c = 0; c < 2; c++) {
        int cc = c0 + c;
        int row = cc >> 2;
        int k4 = (cc & 3) * 4;
        size_t goffA = (size_t)(bm + row) * K + k0 + k4;
        size_t goffB = (size_t)(bn + row) * K + k0 + k4;
        uint32_t so = (uint32_t)__cvta_generic_to_shared(base + row * ALD + k4);
        cp16(so,                  Ah + goffA);
        cp16(so + TILE_F * 4,     Al + goffA);
        cp16(so + 2 * TILE_F * 4, Bh + goffB);
        cp16(so + 3 * TILE_F * 4, Bl + goffB);
    }
    asm volatile("cp.async.commit_group;");
}

__global__ __launch_bounds__(256)
void sgemm_split(const float* __restrict__ Ah, const float* __restrict__ Al,
                 const float* __restrict__ Bh, const float* __restrict__ Bl,
                 float* __restrict__ Cm, int M, int N, int K) {
    extern __shared__ __align__(16) float sm[];

    int t = threadIdx.x;
    int lane = t & 31, w = t >> 5;
    int gid = lane >> 2, tig = lane & 3;
    int mw = (w & 3) * 32;
    int nw = (w >> 2) * 64;
    int bm = blockIdx.y * 128, bn = blockIdx.x * 128;

    float c[2][8][4] = {};

    int nkt = K / 16;
    gemm_load_stage(sm, 0, Ah, Al, Bh, Bl, K, bm, bn, 0, t);

    for (int kt = 0; kt < nkt; kt++) {
        asm volatile("cp.async.wait_group 0;");
        __syncthreads();
        if (kt + 1 < nkt)
            gemm_load_stage(sm, (kt + 1) & 1, Ah, Al, Bh, Bl, K, bm, bn,
                            (kt + 1) * 16, t);
        float* base = sm + (kt & 1) * STAGE_F;
        float* Ahs = base;
        float* Als = base + TILE_F;
        float* Bhs = base + 2 * TILE_F;
        float* Bls = base + 3 * TILE_F;

#pragma unroll
        for (int ks = 0; ks < 2; ks++) {
            int kb = ks * 8;
            uint32_t ah[2][4], al[2][4];
#pragma unroll
            for (int mt = 0; mt < 2; mt++) {
                int row = mw + mt * 16 + gid;
                ah[mt][0] = __float_as_uint(Ahs[row * ALD + kb + tig]);
                ah[mt][1] = __float_as_uint(Ahs[(row + 8) * ALD + kb + tig]);
                ah[mt][2] = __float_as_uint(Ahs[row * ALD + kb + tig + 4]);
                ah[mt][3] = __float_as_uint(Ahs[(row + 8) * ALD + kb + tig + 4]);
                al[mt][0] = __float_as_uint(Als[row * ALD + kb + tig]);
                al[mt][1] = __float_as_uint(Als[(row + 8) * ALD + kb + tig]);
                al[mt][2] = __float_as_uint(Als[row * ALD + kb + tig + 4]);
                al[mt][3] = __float_as_uint(Als[(row + 8) * ALD + kb + tig + 4]);
            }
            uint32_t bh[8][2], bl[8][2];
#pragma unroll
            for (int nt = 0; nt < 8; nt++) {
                int n = nw + nt * 8 + gid;
                bh[nt][0] = __float_as_uint(Bhs[n * ALD + kb + tig]);
                bh[nt][1] = __float_as_uint(Bhs[n * ALD + kb + tig + 4]);
                bl[nt][0] = __float_as_uint(Bls[n * ALD + kb + tig]);
                bl[nt][1] = __float_as_uint(Bls[n * ALD + kb + tig + 4]);
            }
#pragma unroll
            for (int mt = 0; mt < 2; mt++)
#pragma unroll
                for (int nt = 0; nt < 8; nt++) {
                    mma_tf32(c[mt][nt], ah[mt][0], ah[mt][1], ah[mt][2], ah[mt][3],
                             bh[nt][0], bh[nt][1]);
                    mma_tf32(c[mt][nt], ah[mt][0], ah[mt][1], ah[mt][2], ah[mt][3],
                             bl[nt][0], bl[nt][1]);
                    mma_tf32(c[mt][nt], al[mt][0], al[mt][1], al[mt][2], al[mt][3],
                             bh[nt][0], bh[nt][1]);
                }
        }
    }

#pragma unroll
    for (int mt = 0; mt < 2; mt++) {
        int row = bm + mw + mt * 16 + gid;
#pragma unroll
        for (int nt = 0; nt < 8; nt++) {
            int col = bn + nw + nt * 8 + 2 * tig;
            *(float2*)&Cm[(size_t)row * N + col] =
                make_float2(c[mt][nt][0], c[mt][nt][1]);
            *(float2*)&Cm[(size_t)(row + 8) * N + col] =
                make_float2(c[mt][nt][2], c[mt][nt][3]);
        }
    }
}

// ---------------------------------------------------------------------------
// RoPE + split -> tf32-pattern q (pre-scaled by 1/8), k, v in [B,H,T,D]
// ---------------------------------------------------------------------------
__global__ void rope_split_kernel() {
    int i = blockIdx.x * blockDim.x + threadIdx.x;
    int d = i & 63;
    int h = (i >> 6) & 15;
    int t = (i >> 10) & 2047;
    int b = i >> 21;

    const float* base = g_qkv + (size_t)(b * T_SEQ + t) * (3 * C_EMB);
    float cs = g_cos[t * 64 + d];
    float sn = g_sin[t * 64 + d];

    int o  = h * 64 + d;
    int o2 = h * 64 + ((d < 32) ? (d + 32) : (d - 32));
    float sgn = (d < 32) ? -1.f : 1.f;

    float qv = base[o];
    float qp = base[o2];
    float kv = base[C_EMB + o];
    float kp = base[C_EMB + o2];

    size_t oi = ((size_t)(b * NHEAD + h) * T_SEQ + t) * H_DIM + d;
    g_q[oi] = __uint_as_float(f2tf((qv * cs + sgn * qp * sn) * 0.125f));
    g_k[oi] = __uint_as_float(f2tf(kv * cs + sgn * kp * sn));
    g_v[oi] = __uint_as_float(f2tf(base[2 * C_EMB + o]));
}

// ---------------------------------------------------------------------------
// Flash attention (causal), tf32 mma, pre-converted inputs.
// Block 256 threads (8 warps), 128 Q rows (16/warp), 64-key tiles.
// Epilogue writes hi/lo split of y for proj GEMM.
// ---------------------------------------------------------------------------
#define KS_LD 68
#define VS_LD 72
#define PS_LD 68
#define SM_V_OFF (64 * KS_LD)
#define SM_P_OFF (SM_V_OFF + 64 * VS_LD)
#define ATTN_SMEM_FLOATS (SM_P_OFF + 128 * PS_LD)

__global__ __launch_bounds__(256)
void attn_mma_kernel(const float* __restrict__ Q, const float* __restrict__ Kg,
                     const float* __restrict__ Vg,
                     float* __restrict__ Yh, float* __restrict__ Yl) {
    extern __shared__ __align__(16) float sm[];
    float* Ksm = sm;
    float* Vsm = sm + SM_V_OFF;
    float* Psm = sm + SM_P_OFF;

    int t = threadIdx.x;
    int lane = t & 31, w = t >> 5;
    int gid = lane >> 2, tig = lane & 3;
    int qt = blockIdx.x;
    int bh = blockIdx.y;
    int wrow = w * 16;

    const float* Qb = Q  + (size_t)bh * T_SEQ * H_DIM;
    const float* Kb = Kg + (size_t)bh * T_SEQ * H_DIM;
    const float* Vb = Vg + (size_t)bh * T_SEQ * H_DIM;

    int r0g = qt * 128 + wrow + gid;
    int r1g = r0g + 8;
    uint32_t qa[8][4];
    {
        const float* qp0 = Qb + (size_t)r0g * H_DIM;
        const float* qp1 = Qb + (size_t)r1g * H_DIM;
#pragma unroll
        for (int ks = 0; ks < 8; ks++) {
            int kk = ks * 8 + tig;
            qa[ks][0] = __float_as_uint(qp0[kk]);
            qa[ks][1] = __float_as_uint(qp1[kk]);
            qa[ks][2] = __float_as_uint(qp0[kk + 4]);
            qa[ks][3] = __float_as_uint(qp1[kk + 4]);
        }
    }

    float o[8][4] = {};
    float m0 = -INFINITY, m1 = -INFINITY;
    float l0 = 0.f, l1 = 0.f;

    float* pr0 = &Psm[(wrow + gid) * PS_LD];
    float* pr1 = &Psm[(wrow + gid + 8) * PS_LD];

    int ktmax = 2 * qt + 1;
    for (int kt = 0; kt <= ktmax; kt++) {
        __syncthreads();
        {   // load K,V tile (already tf32 bit patterns)
            int row = t >> 2, dc = (t & 3) * 16;
            const float* kp = Kb + ((size_t)kt * 64 + row) * H_DIM + dc;
            const float* vp = Vb + ((size_t)kt * 64 + row) * H_DIM + dc;
#pragma unroll
            for (int j = 0; j < 4; j++) {
                *(float4*)&Ksm[row * KS_LD + dc + j * 4] = *(const float4*)(kp + j * 4);
                *(float4*)&Vsm[row * VS_LD + dc + j * 4] = *(const float4*)(vp + j * 4);
            }
        }
        __syncthreads();

        // S = Q K^T (scale folded into Q)
        float s[8][4] = {};
#pragma unroll
        for (int ks = 0; ks < 8; ks++) {
            int kk = ks * 8 + tig;
#pragma unroll
            for (int nt = 0; nt < 8; nt++) {
                int n = nt * 8 + gid;
                uint32_t b0 = __float_as_uint(Ksm[n * KS_LD + kk]);
                uint32_t b1 = __float_as_uint(Ksm[n * KS_LD + kk + 4]);
                mma_tf32(s[nt], qa[ks][0], qa[ks][1], qa[ks][2], qa[ks][3], b0, b1);
            }
        }

        if (kt * 64 + 63 > qt * 128 + wrow) {
#pragma unroll
            for (int nt = 0; nt < 8; nt++) {
                int col = kt * 64 + nt * 8 + 2 * tig;
                if (col > r0g)     s[nt][0] = -INFINITY;
                if (col + 1 > r0g) s[nt][1] = -INFINITY;
                if (col > r1g)     s[nt][2] = -INFINITY;
                if (col + 1 > r1g) s[nt][3] = -INFINITY;
            }
        }

        float mt0 = -INFINITY, mt1 = -INFINITY;
#pragma unroll
        for (int nt = 0; nt < 8; nt++) {
            mt0 = fmaxf(mt0, fmaxf(s[nt][0], s[nt][1]));
            mt1 = fmaxf(mt1, fmaxf(s[nt][2], s[nt][3]));
        }
        mt0 = fmaxf(mt0, __shfl_xor_sync(0xffffffffu, mt0, 1));
        mt0 = fmaxf(mt0, __shfl_xor_sync(0xffffffffu, mt0, 2));
        mt1 = fmaxf(mt1, __shfl_xor_sync(0xffffffffu, mt1, 1));
        mt1 = fmaxf(mt1, __shfl_xor_sync(0xffffffffu, mt1, 2));

        float mn0 = fmaxf(m0, mt0), mn1 = fmaxf(m1, mt1);
        float al0 = __expf(m0 - mn0), al1 = __expf(m1 - mn1);
        m0 = mn0; m1 = mn1;

        float ls0 = 0.f, ls1 = 0.f;
#pragma unroll
        for (int nt = 0; nt < 8; nt++) {
            s[nt][0] = __expf(s[nt][0] - mn0);
            s[nt][1] = __expf(s[nt][1] - mn0);
            s[nt][2] = __expf(s[nt][2] - mn1);
            s[nt][3] = __expf(s[nt][3] - mn1);
            ls0 += s[nt][0] + s[nt][1];
            ls1 += s[nt][2] + s[nt][3];
        }
        ls0 += __shfl_xor_sync(0xffffffffu, ls0, 1);
        ls0 += __shfl_xor_sync(0xffffffffu, ls0, 2);
        ls1 += __shfl_xor_sync(0xffffffffu, ls1, 1);
        ls1 += __shfl_xor_sync(0xffffffffu, ls1, 2);
        l0 = l0 * al0 + ls0;
        l1 = l1 * al1 + ls1;

#pragma unroll
        for (int nt = 0; nt < 8; nt++) {
            o[nt][0] *= al0; o[nt][1] *= al0;
            o[nt][2] *= al1; o[nt][3] *= al1;
        }

        // stage P as tf32 patterns (convert once here)
#pragma unroll
        for (int nt = 0; nt < 8; nt++) {
            *(float2*)&pr0[nt * 8 + 2 * tig] =
                make_float2(__uint_as_float(f2tf(s[nt][0])), __uint_as_float(f2tf(s[nt][1])));
            *(float2*)&pr1[nt * 8 + 2 * tig] =
                make_float2(__uint_as_float(f2tf(s[nt][2])), __uint_as_float(f2tf(s[nt][3])));
        }
        __syncwarp();

        // O += P * V (pure LDS + mma)
#pragma unroll
        for (int ks = 0; ks < 8; ks++) {
            int kk = ks * 8;
            uint32_t pa0 = __float_as_uint(pr0[kk + tig]);
            uint32_t pa1 = __float_as_uint(pr1[kk + tig]);
            uint32_t pa2 = __float_as_uint(pr0[kk + tig + 4]);
            uint32_t pa3 = __float_as_uint(pr1[kk + tig + 4]);
#pragma unroll
            for (int nt = 0; nt < 8; nt++) {
                int d = nt * 8 + gid;
                uint32_t b0 = __float_as_uint(Vsm[(kk + tig) * VS_LD + d]);
                uint32_t b1 = __float_as_uint(Vsm[(kk + tig + 4) * VS_LD + d]);
                mma_tf32(o[nt], pa0, pa1, pa2, pa3, b0, b1);
            }
        }
        __syncwarp();
    }

    // finalize: divide by l, write hi/lo split into Yh/Yl [B,T,C]
    float inv0 = 1.f / l0, inv1 = 1.f / l1;
    int b = bh >> 4, h = bh & 15;
    size_t off0 = ((size_t)b * T_SEQ + r0g) * C_EMB + h * 64;
    size_t off1 = ((size_t)b * T_SEQ + r1g) * C_EMB + h * 64;
#pragma unroll
    for (int nt = 0; nt < 8; nt++) {
        int col = nt * 8 + 2 * tig;
        float v00 = o[nt][0] * inv0, v01 = o[nt][1] * inv0;
        float v10 = o[nt][2] * inv1, v11 = o[nt][3] * inv1;
        float h00 = __uint_as_float(f2tf(v00));
        float h01 = __uint_as_float(f2tf(v01));
        float h10 = __uint_as_float(f2tf(v10));
        float h11 = __uint_as_float(f2tf(v11));
        *(float2*)&Yh[off0 + col] = make_float2(h00, h01);
        *(float2*)&Yh[off1 + col] = make_float2(h10, h11);
        *(float2*)&Yl[off0 + col] = make_float2(__uint_as_float(f2tf(v00 - h00)),
                                                __uint_as_float(f2tf(v01 - h01)));
        *(float2*)&Yl[off1 + col] = make_float2(__uint_as_float(f2tf(v10 - h10)),
                                                __uint_as_float(f2tf(v11 - h11)));
    }
}

// ---------------------------------------------------------------------------
extern "C" void kernel_launch(void* const* d_in, const int* in_sizes, int n_in,
                              void* d_out, int out_size) {
    const float* x      = (const float*)d_in[0];
    const float* w_qkv  = (const float*)d_in[1];
    const float* w_proj = (const float*)d_in[2];
    float* out = (float*)d_out;

    float *p_qkv, *p_xh, *p_xl, *p_wqh, *p_wql, *p_wph, *p_wpl;
    float *p_q, *p_k, *p_v, *p_yh, *p_yl;
    cudaGetSymbolAddress((void**)&p_qkv, g_qkv);
    cudaGetSymbolAddress((void**)&p_xh, g_xh);
    cudaGetSymbolAddress((void**)&p_xl, g_xl);
    cudaGetSymbolAddress((void**)&p_wqh, g_wqh);
    cudaGetSymbolAddress((void**)&p_wql, g_wql);
    cudaGetSymbolAddress((void**)&p_wph, g_wph);
    cudaGetSymbolAddress((void**)&p_wpl, g_wpl);
    cudaGetSymbolAddress((void**)&p_q, g_q);
    cudaGetSymbolAddress((void**)&p_k, g_k);
    cudaGetSymbolAddress((void**)&p_v, g_v);
    cudaGetSymbolAddress((void**)&p_yh, g_yh);
    cudaGetSymbolAddress((void**)&p_yl, g_yl);

    // RoPE tables + input splits
    rope_table_kernel<<<(T_SEQ * H_DIM + 255) / 256, 256>>>();
    split_kernel<<<(M_TOT * C_EMB + 255) / 256, 256>>>(x, p_xh, p_xl, M_TOT * C_EMB);
    split_kernel<<<(3 * C_EMB * C_EMB + 255) / 256, 256>>>(w_qkv, p_wqh, p_wql,
                                                           3 * C_EMB * C_EMB);
    split_kernel<<<(C_EMB * C_EMB + 255) / 256, 256>>>(w_proj, p_wph, p_wpl,
                                                       C_EMB * C_EMB);

    cudaFuncSetAttribute(sgemm_split,
                         cudaFuncAttributeMaxDynamicSharedMemorySize, GEMM_SMEM_BYTES);

    // QKV GEMM
    sgemm_split<<<dim3((3 * C_EMB) / 128, M_TOT / 128), 256, GEMM_SMEM_BYTES>>>(
        p_xh, p_xl, p_wqh, p_wql, p_qkv, M_TOT, 3 * C_EMB, C_EMB);

    // RoPE + split into tf32 [B,H,T,D]
    rope_split_kernel<<<(B_SZ * T_SEQ * C_EMB) / 256, 256>>>();

    // Flash attention
    int smem_bytes = ATTN_SMEM_FLOATS * 4;
    cudaFuncSetAttribute(attn_mma_kernel,
                         cudaFuncAttributeMaxDynamicSharedMemorySize, smem_bytes);
    attn_mma_kernel<<<dim3(T_SEQ / 128, B_SZ * NHEAD), 256, smem_bytes>>>(
        p_q, p_k, p_v, p_yh, p_yl);

    // Proj GEMM
    sgemm_split<<<dim3(C_EMB / 128, M_TOT / 128), 256, GEMM_SMEM_BYTES>>>(
        p_yh, p_yl, p_wph, p_wpl, out, M_TOT, C_EMB, C_EMB);
}

// round 8
// speedup vs baseline: 1.6697x; 1.6697x over previous
#include <cuda_runtime.h>
#include <math.h>
#include <stdint.h>

#define B_SZ   2
#define T_SEQ  2048
#define C_EMB  1024
#define NHEAD  16
#define H_DIM  64
#define M_TOT  (B_SZ * T_SEQ)   // 4096

// Scratch (static device arrays)
__device__ float g_qkv[(size_t)M_TOT * 3 * C_EMB];           // [B,T,3C] fp32
__device__ float g_xt[(size_t)M_TOT * C_EMB];                // tf32 patterns
__device__ float g_wqt[(size_t)3 * C_EMB * C_EMB];
__device__ float g_wpt[(size_t)C_EMB * C_EMB];
__device__ float g_q[(size_t)B_SZ * NHEAD * T_SEQ * H_DIM];  // tf32 pattern, pre-scaled
__device__ float g_k[(size_t)B_SZ * NHEAD * T_SEQ * H_DIM];  // tf32 pattern
__device__ float g_v[(size_t)B_SZ * NHEAD * T_SEQ * H_DIM];  // tf32 pattern
__device__ float g_yt[(size_t)M_TOT * C_EMB];                // tf32 pattern
__device__ float g_cos[T_SEQ * H_DIM];
__device__ float g_sin[T_SEQ * H_DIM];

// ---------------------------------------------------------------------------
__device__ __forceinline__ uint32_t f2tf(float x) {
    uint32_t r;
    asm("cvt.rna.tf32.f32 %0, %1;" : "=r"(r) : "f"(x));
    return r;
}
__device__ __forceinline__ void mma_tf32(float* c,
                                         uint32_t a0, uint32_t a1, uint32_t a2, uint32_t a3,
                                         uint32_t b0, uint32_t b1) {
    asm volatile(
        "mma.sync.aligned.m16n8k8.row.col.f32.tf32.tf32.f32 "
        "{%0,%1,%2,%3}, {%4,%5,%6,%7}, {%8,%9}, {%0,%1,%2,%3};"
        : "+f"(c[0]), "+f"(c[1]), "+f"(c[2]), "+f"(c[3])
        : "r"(a0), "r"(a1), "r"(a2), "r"(a3), "r"(b0), "r"(b1));
}
__device__ __forceinline__ void cp16(uint32_t saddr, const void* g) {
    asm volatile("cp.async.cg.shared.global [%0], [%1], 16;" :: "r"(saddr), "l"(g));
}

// ---------------------------------------------------------------------------
// fp32 -> tf32 bit-pattern convert (vectorized)
// ---------------------------------------------------------------------------
__global__ void cvt_kernel(const float4* __restrict__ src,
                           float4* __restrict__ dst, int n4) {
    int i = blockIdx.x * blockDim.x + threadIdx.x;
    if (i >= n4) return;
    float4 v = src[i];
    v.x = __uint_as_float(f2tf(v.x));
    v.y = __uint_as_float(f2tf(v.y));
    v.z = __uint_as_float(f2tf(v.z));
    v.w = __uint_as_float(f2tf(v.w));
    dst[i] = v;
}

// ---------------------------------------------------------------------------
// RoPE table
// ---------------------------------------------------------------------------
__global__ void rope_table_kernel() {
    int i = blockIdx.x * blockDim.x + threadIdx.x;
    if (i >= T_SEQ * H_DIM) return;
    int t = i >> 6;
    int d = i & 63;
    double f = pow(10000.0, -(double)(d & 31) / 32.0);
    double ang = (double)t * f;
    g_cos[i] = (float)cos(ang);
    g_sin[i] = (float)sin(ang);
}

// ---------------------------------------------------------------------------
// Single-pass tf32 SGEMM: C[M,N] = A[M,K] * B[N,K]^T
// A,B already tf32 bit patterns. 128x128 tile, BK=16, 256 threads,
// warp tile 32x64, cp.async 2-stage double buffer. 40KB smem.
// ---------------------------------------------------------------------------
#define ALD 20
#define TILE_F (128 * ALD)          // 2560
#define STAGE_F (2 * TILE_F)        // 5120
#define GEMM_SMEM_BYTES (2 * STAGE_F * 4)  // 40960

__device__ __forceinline__ void gemm_load_stage(
    float* sm, int s, const float* A, const float* B,
    int K, int bm, int bn, int k0, int t) {
    float* base = sm + s * STAGE_F;
#pragma unroll
    for (int c = 0; c < 2; c++) {
        int cc = t * 2 + c;
        int row = cc >> 2;
        int k4 = (cc & 3) * 4;
        uint32_t so = (uint32_t)__cvta_generic_to_shared(base + row * ALD + k4);
        cp16(so,              A + (size_t)(bm + row) * K + k0 + k4);
        cp16(so + TILE_F * 4, B + (size_t)(bn + row) * K + k0 + k4);
    }
    asm volatile("cp.async.commit_group;");
}

__global__ __launch_bounds__(256)
void sgemm_tf32(const float* __restrict__ A, const float* __restrict__ B,
                float* __restrict__ Cm, int M, int N, int K) {
    extern __shared__ __align__(16) float sm[];

    int t = threadIdx.x;
    int lane = t & 31, w = t >> 5;
    int gid = lane >> 2, tig = lane & 3;
    int mw = (w & 3) * 32;
    int nw = (w >> 2) * 64;
    int bm = blockIdx.y * 128, bn = blockIdx.x * 128;

    float c[2][8][4] = {};

    int nkt = K / 16;
    gemm_load_stage(sm, 0, A, B, K, bm, bn, 0, t);

    for (int kt = 0; kt < nkt; kt++) {
        asm volatile("cp.async.wait_group 0;");
        __syncthreads();
        if (kt + 1 < nkt)
            gemm_load_stage(sm, (kt + 1) & 1, A, B, K, bm, bn, (kt + 1) * 16, t);
        float* As = sm + (kt & 1) * STAGE_F;
        float* Bs = As + TILE_F;

#pragma unroll
        for (int ks = 0; ks < 2; ks++) {
            int kb = ks * 8;
            uint32_t ah[2][4];
#pragma unroll
            for (int mt = 0; mt < 2; mt++) {
                int row = mw + mt * 16 + gid;
                ah[mt][0] = __float_as_uint(As[row * ALD + kb + tig]);
                ah[mt][1] = __float_as_uint(As[(row + 8) * ALD + kb + tig]);
                ah[mt][2] = __float_as_uint(As[row * ALD + kb + tig + 4]);
                ah[mt][3] = __float_as_uint(As[(row + 8) * ALD + kb + tig + 4]);
            }
            uint32_t bh[8][2];
#pragma unroll
            for (int nt = 0; nt < 8; nt++) {
                int n = nw + nt * 8 + gid;
                bh[nt][0] = __float_as_uint(Bs[n * ALD + kb + tig]);
                bh[nt][1] = __float_as_uint(Bs[n * ALD + kb + tig + 4]);
            }
#pragma unroll
            for (int mt = 0; mt < 2; mt++)
#pragma unroll
                for (int nt = 0; nt < 8; nt++)
                    mma_tf32(c[mt][nt], ah[mt][0], ah[mt][1], ah[mt][2], ah[mt][3],
                             bh[nt][0], bh[nt][1]);
        }
    }

#pragma unroll
    for (int mt = 0; mt < 2; mt++) {
        int row = bm + mw + mt * 16 + gid;
#pragma unroll
        for (int nt = 0; nt < 8; nt++) {
            int col = bn + nw + nt * 8 + 2 * tig;
            *(float2*)&Cm[(size_t)row * N + col] =
                make_float2(c[mt][nt][0], c[mt][nt][1]);
            *(float2*)&Cm[(size_t)(row + 8) * N + col] =
                make_float2(c[mt][nt][2], c[mt][nt][3]);
        }
    }
}

// ---------------------------------------------------------------------------
// RoPE + split -> tf32-pattern q (pre-scaled by 1/8), k, v in [B,H,T,D]
// ---------------------------------------------------------------------------
__global__ void rope_split_kernel() {
    int i = blockIdx.x * blockDim.x + threadIdx.x;
    int d = i & 63;
    int h = (i >> 6) & 15;
    int t = (i >> 10) & 2047;
    int b = i >> 21;

    const float* base = g_qkv + (size_t)(b * T_SEQ + t) * (3 * C_EMB);
    float cs = g_cos[t * 64 + d];
    float sn = g_sin[t * 64 + d];

    int o  = h * 64 + d;
    int o2 = h * 64 + ((d < 32) ? (d + 32) : (d - 32));
    float sgn = (d < 32) ? -1.f : 1.f;

    float qv = base[o];
    float qp = base[o2];
    float kv = base[C_EMB + o];
    float kp = base[C_EMB + o2];

    size_t oi = ((size_t)(b * NHEAD + h) * T_SEQ + t) * H_DIM + d;
    g_q[oi] = __uint_as_float(f2tf((qv * cs + sgn * qp * sn) * 0.125f));
    g_k[oi] = __uint_as_float(f2tf(kv * cs + sgn * kp * sn));
    g_v[oi] = __uint_as_float(f2tf(base[2 * C_EMB + o]));
}

// ---------------------------------------------------------------------------
// Flash attention (causal), tf32 mma, pre-converted inputs.
// Block 256 threads (8 warps), 128 Q rows (16/warp), 64-key tiles.
// Epilogue writes y as tf32 pattern for the proj GEMM.
// ---------------------------------------------------------------------------
#define KS_LD 68
#define VS_LD 72
#define PS_LD 68
#define SM_V_OFF (64 * KS_LD)
#define SM_P_OFF (SM_V_OFF + 64 * VS_LD)
#define ATTN_SMEM_FLOATS (SM_P_OFF + 128 * PS_LD)

__global__ __launch_bounds__(256)
void attn_mma_kernel(const float* __restrict__ Q, const float* __restrict__ Kg,
                     const float* __restrict__ Vg, float* __restrict__ Yt) {
    extern __shared__ __align__(16) float sm[];
    float* Ksm = sm;
    float* Vsm = sm + SM_V_OFF;
    float* Psm = sm + SM_P_OFF;

    int t = threadIdx.x;
    int lane = t & 31, w = t >> 5;
    int gid = lane >> 2, tig = lane & 3;
    int qt = blockIdx.x;
    int bh = blockIdx.y;
    int wrow = w * 16;

    const float* Qb = Q  + (size_t)bh * T_SEQ * H_DIM;
    const float* Kb = Kg + (size_t)bh * T_SEQ * H_DIM;
    const float* Vb = Vg + (size_t)bh * T_SEQ * H_DIM;

    int r0g = qt * 128 + wrow + gid;
    int r1g = r0g + 8;
    uint32_t qa[8][4];
    {
        const float* qp0 = Qb + (size_t)r0g * H_DIM;
        const float* qp1 = Qb + (size_t)r1g * H_DIM;
#pragma unroll
        for (int ks = 0; ks < 8; ks++) {
            int kk = ks * 8 + tig;
            qa[ks][0] = __float_as_uint(qp0[kk]);
            qa[ks][1] = __float_as_uint(qp1[kk]);
            qa[ks][2] = __float_as_uint(qp0[kk + 4]);
            qa[ks][3] = __float_as_uint(qp1[kk + 4]);
        }
    }

    float o[8][4] = {};
    float m0 = -INFINITY, m1 = -INFINITY;
    float l0 = 0.f, l1 = 0.f;

    float* pr0 = &Psm[(wrow + gid) * PS_LD];
    float* pr1 = &Psm[(wrow + gid + 8) * PS_LD];

    int ktmax = 2 * qt + 1;
    for (int kt = 0; kt <= ktmax; kt++) {
        __syncthreads();
        {   // load K,V tile (already tf32 bit patterns)
            int row = t >> 2, dc = (t & 3) * 16;
            const float* kp = Kb + ((size_t)kt * 64 + row) * H_DIM + dc;
            const float* vp = Vb + ((size_t)kt * 64 + row) * H_DIM + dc;
#pragma unroll
            for (int j = 0; j < 4; j++) {
                *(float4*)&Ksm[row * KS_LD + dc + j * 4] = *(const float4*)(kp + j * 4);
                *(float4*)&Vsm[row * VS_LD + dc + j * 4] = *(const float4*)(vp + j * 4);
            }
        }
        __syncthreads();

        // S = Q K^T (scale folded into Q)
        float s[8][4] = {};
#pragma unroll
        for (int ks = 0; ks < 8; ks++) {
            int kk = ks * 8 + tig;
#pragma unroll
            for (int nt = 0; nt < 8; nt++) {
                int n = nt * 8 + gid;
                uint32_t b0 = __float_as_uint(Ksm[n * KS_LD + kk]);
                uint32_t b1 = __float_as_uint(Ksm[n * KS_LD + kk + 4]);
                mma_tf32(s[nt], qa[ks][0], qa[ks][1], qa[ks][2], qa[ks][3], b0, b1);
            }
        }

        if (kt * 64 + 63 > qt * 128 + wrow) {
#pragma unroll
            for (int nt = 0; nt < 8; nt++) {
                int col = kt * 64 + nt * 8 + 2 * tig;
                if (col > r0g)     s[nt][0] = -INFINITY;
                if (col + 1 > r0g) s[nt][1] = -INFINITY;
                if (col > r1g)     s[nt][2] = -INFINITY;
                if (col + 1 > r1g) s[nt][3] = -INFINITY;
            }
        }

        float mt0 = -INFINITY, mt1 = -INFINITY;
#pragma unroll
        for (int nt = 0; nt < 8; nt++) {
            mt0 = fmaxf(mt0, fmaxf(s[nt][0], s[nt][1]));
            mt1 = fmaxf(mt1, fmaxf(s[nt][2], s[nt][3]));
        }
        mt0 = fmaxf(mt0, __shfl_xor_sync(0xffffffffu, mt0, 1));
        mt0 = fmaxf(mt0, __shfl_xor_sync(0xffffffffu, mt0, 2));
        mt1 = fmaxf(mt1, __shfl_xor_sync(0xffffffffu, mt1, 1));
        mt1 = fmaxf(mt1, __shfl_xor_sync(0xffffffffu, mt1, 2));

        float mn0 = fmaxf(m0, mt0), mn1 = fmaxf(m1, mt1);
        float al0 = __expf(m0 - mn0), al1 = __expf(m1 - mn1);
        m0 = mn0; m1 = mn1;

        float ls0 = 0.f, ls1 = 0.f;
#pragma unroll
        for (int nt = 0; nt < 8; nt++) {
            s[nt][0] = __expf(s[nt][0] - mn0);
            s[nt][1] = __expf(s[nt][1] - mn0);
            s[nt][2] = __expf(s[nt][2] - mn1);
            s[nt][3] = __expf(s[nt][3] - mn1);
            ls0 += s[nt][0] + s[nt][1];
            ls1 += s[nt][2] + s[nt][3];
        }
        ls0 += __shfl_xor_sync(0xffffffffu, ls0, 1);
        ls0 += __shfl_xor_sync(0xffffffffu, ls0, 2);
        ls1 += __shfl_xor_sync(0xffffffffu, ls1, 1);
        ls1 += __shfl_xor_sync(0xffffffffu, ls1, 2);
        l0 = l0 * al0 + ls0;
        l1 = l1 * al1 + ls1;

#pragma unroll
        for (int nt = 0; nt < 8; nt++) {
            o[nt][0] *= al0; o[nt][1] *= al0;
            o[nt][2] *= al1; o[nt][3] *= al1;
        }

        // stage P as tf32 patterns (convert once here)
#pragma unroll
        for (int nt = 0; nt < 8; nt++) {
            *(float2*)&pr0[nt * 8 + 2 * tig] =
                make_float2(__uint_as_float(f2tf(s[nt][0])), __uint_as_float(f2tf(s[nt][1])));
            *(float2*)&pr1[nt * 8 + 2 * tig] =
                make_float2(__uint_as_float(f2tf(s[nt][2])), __uint_as_float(f2tf(s[nt][3])));
        }
        __syncwarp();

        // O += P * V (pure LDS + mma)
#pragma unroll
        for (int ks = 0; ks < 8; ks++) {
            int kk = ks * 8;
            uint32_t pa0 = __float_as_uint(pr0[kk + tig]);
            uint32_t pa1 = __float_as_uint(pr1[kk + tig]);
            uint32_t pa2 = __float_as_uint(pr0[kk + tig + 4]);
            uint32_t pa3 = __float_as_uint(pr1[kk + tig + 4]);
#pragma unroll
            for (int nt = 0; nt < 8; nt++) {
                int d = nt * 8 + gid;
                uint32_t b0 = __float_as_uint(Vsm[(kk + tig) * VS_LD + d]);
                uint32_t b1 = __float_as_uint(Vsm[(kk + tig + 4) * VS_LD + d]);
                mma_tf32(o[nt], pa0, pa1, pa2, pa3, b0, b1);
            }
        }
        __syncwarp();
    }

    // finalize: divide by l, write tf32 pattern into Yt [B,T,C]
    float inv0 = 1.f / l0, inv1 = 1.f / l1;
    int b = bh >> 4, h = bh & 15;
    size_t off0 = ((size_t)b * T_SEQ + r0g) * C_EMB + h * 64;
    size_t off1 = ((size_t)b * T_SEQ + r1g) * C_EMB + h * 64;
#pragma unroll
    for (int nt = 0; nt < 8; nt++) {
        int col = nt * 8 + 2 * tig;
        *(float2*)&Yt[off0 + col] =
            make_float2(__uint_as_float(f2tf(o[nt][0] * inv0)),
                        __uint_as_float(f2tf(o[nt][1] * inv0)));
        *(float2*)&Yt[off1 + col] =
            make_float2(__uint_as_float(f2tf(o[nt][2] * inv1)),
                        __uint_as_float(f2tf(o[nt][3] * inv1)));
    }
}

// ---------------------------------------------------------------------------
extern "C" void kernel_launch(void* const* d_in, const int* in_sizes, int n_in,
                              void* d_out, int out_size) {
    const float* x      = (const float*)d_in[0];
    const float* w_qkv  = (const float*)d_in[1];
    const float* w_proj = (const float*)d_in[2];
    float* out = (float*)d_out;

    float *p_qkv, *p_xt, *p_wqt, *p_wpt, *p_q, *p_k, *p_v, *p_yt;
    cudaGetSymbolAddress((void**)&p_qkv, g_qkv);
    cudaGetSymbolAddress((void**)&p_xt, g_xt);
    cudaGetSymbolAddress((void**)&p_wqt, g_wqt);
    cudaGetSymbolAddress((void**)&p_wpt, g_wpt);
    cudaGetSymbolAddress((void**)&p_q, g_q);
    cudaGetSymbolAddress((void**)&p_k, g_k);
    cudaGetSymbolAddress((void**)&p_v, g_v);
    cudaGetSymbolAddress((void**)&p_yt, g_yt);

    // RoPE tables + tf32 pre-conversion
    rope_table_kernel<<<(T_SEQ * H_DIM + 255) / 256, 256>>>();
    cvt_kernel<<<(M_TOT * C_EMB / 4 + 255) / 256, 256>>>(
        (const float4*)x, (float4*)p_xt, M_TOT * C_EMB / 4);
    cvt_kernel<<<(3 * C_EMB * C_EMB / 4 + 255) / 256, 256>>>(
        (const float4*)w_qkv, (float4*)p_wqt, 3 * C_EMB * C_EMB / 4);
    cvt_kernel<<<(C_EMB * C_EMB / 4 + 255) / 256, 256>>>(
        (const float4*)w_proj, (float4*)p_wpt, C_EMB * C_EMB / 4);

    cudaFuncSetAttribute(sgemm_tf32,
                         cudaFuncAttributeMaxDynamicSharedMemorySize, GEMM_SMEM_BYTES);

    // QKV GEMM: [4096,1024] x [3072,1024]^T -> [4096,3072]
    sgemm_tf32<<<dim3((3 * C_EMB) / 128, M_TOT / 128), 256, GEMM_SMEM_BYTES>>>(
        p_xt, p_wqt, p_qkv, M_TOT, 3 * C_EMB, C_EMB);

    // RoPE + split into tf32 [B,H,T,D]
    rope_split_kernel<<<(B_SZ * T_SEQ * C_EMB) / 256, 256>>>();

    // Flash attention
    int smem_bytes = ATTN_SMEM_FLOATS * 4;
    cudaFuncSetAttribute(attn_mma_kernel,
                         cudaFuncAttributeMaxDynamicSharedMemorySize, smem_bytes);
    attn_mma_kernel<<<dim3(T_SEQ / 128, B_SZ * NHEAD), 256, smem_bytes>>>(
        p_q, p_k, p_v, p_yt);

    // Proj GEMM: [4096,1024] x [1024,1024]^T -> out
    sgemm_tf32<<<dim3(C_EMB / 128, M_TOT / 128), 256, GEMM_SMEM_BYTES>>>(
        p_yt, p_wpt, out, M_TOT, C_EMB, C_EMB);
}

// round 9
// speedup vs baseline: 1.7671x; 1.0583x over previous
#include <cuda_runtime.h>
#include <math.h>
#include <stdint.h>

#define B_SZ   2
#define T_SEQ  2048
#define C_EMB  1024
#define NHEAD  16
#define H_DIM  64
#define M_TOT  (B_SZ * T_SEQ)   // 4096

// Scratch (static device arrays)
__device__ float g_qkv[(size_t)M_TOT * 3 * C_EMB];           // [B,T,3C] fp32
__device__ float g_xt[(size_t)M_TOT * C_EMB];                // tf32 patterns
__device__ float g_wqt[(size_t)3 * C_EMB * C_EMB];
__device__ float g_wpt[(size_t)C_EMB * C_EMB];
__device__ float g_q[(size_t)B_SZ * NHEAD * T_SEQ * H_DIM];  // tf32 pattern, pre-scaled
__device__ float g_k[(size_t)B_SZ * NHEAD * T_SEQ * H_DIM];  // tf32 pattern
__device__ float g_v[(size_t)B_SZ * NHEAD * T_SEQ * H_DIM];  // tf32 pattern
__device__ float g_yt[(size_t)M_TOT * C_EMB];                // tf32 pattern
__device__ float g_cos[T_SEQ * H_DIM];
__device__ float g_sin[T_SEQ * H_DIM];

// ---------------------------------------------------------------------------
__device__ __forceinline__ uint32_t f2tf(float x) {
    uint32_t r;
    asm("cvt.rna.tf32.f32 %0, %1;" : "=r"(r) : "f"(x));
    return r;
}
__device__ __forceinline__ void mma_tf32(float* c,
                                         uint32_t a0, uint32_t a1, uint32_t a2, uint32_t a3,
                                         uint32_t b0, uint32_t b1) {
    asm volatile(
        "mma.sync.aligned.m16n8k8.row.col.f32.tf32.tf32.f32 "
        "{%0,%1,%2,%3}, {%4,%5,%6,%7}, {%8,%9}, {%0,%1,%2,%3};"
        : "+f"(c[0]), "+f"(c[1]), "+f"(c[2]), "+f"(c[3])
        : "r"(a0), "r"(a1), "r"(a2), "r"(a3), "r"(b0), "r"(b1));
}
__device__ __forceinline__ void cp16(uint32_t saddr, const void* g) {
    asm volatile("cp.async.cg.shared.global [%0], [%1], 16;" :: "r"(saddr), "l"(g));
}

// ---------------------------------------------------------------------------
// fp32 -> tf32 bit-pattern convert (vectorized)
// ---------------------------------------------------------------------------
__global__ void cvt_kernel(const float4* __restrict__ src,
                           float4* __restrict__ dst, int n4) {
    int i = blockIdx.x * blockDim.x + threadIdx.x;
    if (i >= n4) return;
    float4 v = src[i];
    v.x = __uint_as_float(f2tf(v.x));
    v.y = __uint_as_float(f2tf(v.y));
    v.z = __uint_as_float(f2tf(v.z));
    v.w = __uint_as_float(f2tf(v.w));
    dst[i] = v;
}

// ---------------------------------------------------------------------------
// RoPE table
// ---------------------------------------------------------------------------
__global__ void rope_table_kernel() {
    int i = blockIdx.x * blockDim.x + threadIdx.x;
    if (i >= T_SEQ * H_DIM) return;
    int t = i >> 6;
    int d = i & 63;
    double f = pow(10000.0, -(double)(d & 31) / 32.0);
    double ang = (double)t * f;
    g_cos[i] = (float)cos(ang);
    g_sin[i] = (float)sin(ang);
}

// ---------------------------------------------------------------------------
// Single-pass tf32 SGEMM: C[M,N] = A[M,K] * B[N,K]^T
// 128x128 tile, BK=16, 256 threads, warp tile 32x64, 3-stage cp.async.
// ---------------------------------------------------------------------------
#define ALD 20
#define TILE_F (128 * ALD)          // 2560
#define STAGE_F (2 * TILE_F)        // 5120
#define GEMM_SMEM_BYTES (3 * STAGE_F * 4)  // 61440

__device__ __forceinline__ void gemm_load_stage(
    float* sm, int s, const float* A, const float* B,
    int K, int bm, int bn, int k0, int t) {
    float* base = sm + s * STAGE_F;
#pragma unroll
    for (int c = 0; c < 2; c++) {
        int cc = t * 2 + c;
        int row = cc >> 2;
        int k4 = (cc & 3) * 4;
        uint32_t so = (uint32_t)__cvta_generic_to_shared(base + row * ALD + k4);
        cp16(so,              A + (size_t)(bm + row) * K + k0 + k4);
        cp16(so + TILE_F * 4, B + (size_t)(bn + row) * K + k0 + k4);
    }
    asm volatile("cp.async.commit_group;");
}

__global__ __launch_bounds__(256)
void sgemm_tf32(const float* __restrict__ A, const float* __restrict__ B,
                float* __restrict__ Cm, int M, int N, int K) {
    extern __shared__ __align__(16) float sm[];

    int t = threadIdx.x;
    int lane = t & 31, w = t >> 5;
    int gid = lane >> 2, tig = lane & 3;
    int mw = (w & 3) * 32;
    int nw = (w >> 2) * 64;
    int bm = blockIdx.y * 128, bn = blockIdx.x * 128;

    float c[2][8][4] = {};

    int nkt = K / 16;
    gemm_load_stage(sm, 0, A, B, K, bm, bn, 0, t);
    gemm_load_stage(sm, 1, A, B, K, bm, bn, 16, t);

    for (int kt = 0; kt < nkt; kt++) {
        asm volatile("cp.async.wait_group 1;");
        __syncthreads();
        if (kt + 2 < nkt)
            gemm_load_stage(sm, (kt + 2) % 3, A, B, K, bm, bn, (kt + 2) * 16, t);
        else
            asm volatile("cp.async.commit_group;");
        float* As = sm + (kt % 3) * STAGE_F;
        float* Bs = As + TILE_F;

#pragma unroll
        for (int ks = 0; ks < 2; ks++) {
            int kb = ks * 8;
            uint32_t ah[2][4];
#pragma unroll
            for (int mt = 0; mt < 2; mt++) {
                int row = mw + mt * 16 + gid;
                ah[mt][0] = __float_as_uint(As[row * ALD + kb + tig]);
                ah[mt][1] = __float_as_uint(As[(row + 8) * ALD + kb + tig]);
                ah[mt][2] = __float_as_uint(As[row * ALD + kb + tig + 4]);
                ah[mt][3] = __float_as_uint(As[(row + 8) * ALD + kb + tig + 4]);
            }
            uint32_t bh[8][2];
#pragma unroll
            for (int nt = 0; nt < 8; nt++) {
                int n = nw + nt * 8 + gid;
                bh[nt][0] = __float_as_uint(Bs[n * ALD + kb + tig]);
                bh[nt][1] = __float_as_uint(Bs[n * ALD + kb + tig + 4]);
            }
#pragma unroll
            for (int mt = 0; mt < 2; mt++)
#pragma unroll
                for (int nt = 0; nt < 8; nt++)
                    mma_tf32(c[mt][nt], ah[mt][0], ah[mt][1], ah[mt][2], ah[mt][3],
                             bh[nt][0], bh[nt][1]);
        }
    }

#pragma unroll
    for (int mt = 0; mt < 2; mt++) {
        int row = bm + mw + mt * 16 + gid;
#pragma unroll
        for (int nt = 0; nt < 8; nt++) {
            int col = bn + nw + nt * 8 + 2 * tig;
            *(float2*)&Cm[(size_t)row * N + col] =
                make_float2(c[mt][nt][0], c[mt][nt][1]);
            *(float2*)&Cm[(size_t)(row + 8) * N + col] =
                make_float2(c[mt][nt][2], c[mt][nt][3]);
        }
    }
}

// ---------------------------------------------------------------------------
// RoPE + split -> tf32-pattern q (pre-scaled by 1/8), k, v in [B,H,T,D]
// ---------------------------------------------------------------------------
__global__ void rope_split_kernel() {
    int i = blockIdx.x * blockDim.x + threadIdx.x;
    int d = i & 63;
    int h = (i >> 6) & 15;
    int t = (i >> 10) & 2047;
    int b = i >> 21;

    const float* base = g_qkv + (size_t)(b * T_SEQ + t) * (3 * C_EMB);
    float cs = g_cos[t * 64 + d];
    float sn = g_sin[t * 64 + d];

    int o  = h * 64 + d;
    int o2 = h * 64 + ((d < 32) ? (d + 32) : (d - 32));
    float sgn = (d < 32) ? -1.f : 1.f;

    float qv = base[o];
    float qp = base[o2];
    float kv = base[C_EMB + o];
    float kp = base[C_EMB + o2];

    size_t oi = ((size_t)(b * NHEAD + h) * T_SEQ + t) * H_DIM + d;
    g_q[oi] = __uint_as_float(f2tf((qv * cs + sgn * qp * sn) * 0.125f));
    g_k[oi] = __uint_as_float(f2tf(kv * cs + sgn * kp * sn));
    g_v[oi] = __uint_as_float(f2tf(base[2 * C_EMB + o]));
}

// ---------------------------------------------------------------------------
// Flash attention (causal), tf32 mma, cp.async double-buffered K/V.
// Block 256 threads (8 warps), 128 Q rows (16/warp), 64-key tiles.
// Smem: Ksm[2][64*68] + Vsm[2][64*72] + Psm[128*68] = 26624 floats (104 KB).
// ---------------------------------------------------------------------------
#define KS_LD 68
#define VS_LD 72
#define PS_LD 68
#define KT_F (64 * KS_LD)                 // 4352
#define VT_F (64 * VS_LD)                 // 4608
#define SM_V_OFF (2 * KT_F)               // after both K stages
#define SM_P_OFF (SM_V_OFF + 2 * VT_F)
#define ATTN_SMEM_FLOATS (SM_P_OFF + 128 * PS_LD)

__device__ __forceinline__ void attn_load_tile(
    float* Ksm, float* Vsm, const float* Kb, const float* Vb, int kt, int t) {
    int row = t >> 2, dc = (t & 3) * 16;
    const float* kp = Kb + ((size_t)kt * 64 + row) * H_DIM + dc;
    const float* vp = Vb + ((size_t)kt * 64 + row) * H_DIM + dc;
    uint32_t ks = (uint32_t)__cvta_generic_to_shared(Ksm + row * KS_LD + dc);
    uint32_t vs = (uint32_t)__cvta_generic_to_shared(Vsm + row * VS_LD + dc);
#pragma unroll
    for (int j = 0; j < 4; j++) {
        cp16(ks + j * 16, kp + j * 4);
        cp16(vs + j * 16, vp + j * 4);
    }
    asm volatile("cp.async.commit_group;");
}

__global__ __launch_bounds__(256)
void attn_mma_kernel(const float* __restrict__ Q, const float* __restrict__ Kg,
                     const float* __restrict__ Vg, float* __restrict__ Yt) {
    extern __shared__ __align__(16) float sm[];
    float* Psm = sm + SM_P_OFF;

    int t = threadIdx.x;
    int lane = t & 31, w = t >> 5;
    int gid = lane >> 2, tig = lane & 3;
    int qt = blockIdx.x;
    int bh = blockIdx.y;
    int wrow = w * 16;

    const float* Qb = Q  + (size_t)bh * T_SEQ * H_DIM;
    const float* Kb = Kg + (size_t)bh * T_SEQ * H_DIM;
    const float* Vb = Vg + (size_t)bh * T_SEQ * H_DIM;

    int r0g = qt * 128 + wrow + gid;
    int r1g = r0g + 8;
    uint32_t qa[8][4];
    {
        const float* qp0 = Qb + (size_t)r0g * H_DIM;
        const float* qp1 = Qb + (size_t)r1g * H_DIM;
#pragma unroll
        for (int ks = 0; ks < 8; ks++) {
            int kk = ks * 8 + tig;
            qa[ks][0] = __float_as_uint(qp0[kk]);
            qa[ks][1] = __float_as_uint(qp1[kk]);
            qa[ks][2] = __float_as_uint(qp0[kk + 4]);
            qa[ks][3] = __float_as_uint(qp1[kk + 4]);
        }
    }

    float o[8][4] = {};
    float m0 = -INFINITY, m1 = -INFINITY;
    float l0 = 0.f, l1 = 0.f;

    float* pr0 = &Psm[(wrow + gid) * PS_LD];
    float* pr1 = &Psm[(wrow + gid + 8) * PS_LD];

    int ktmax = 2 * qt + 1;
    attn_load_tile(sm, sm + SM_V_OFF, Kb, Vb, 0, t);

    for (int kt = 0; kt <= ktmax; kt++) {
        asm volatile("cp.async.wait_group 0;");
        __syncthreads();
        if (kt + 1 <= ktmax)
            attn_load_tile(sm + ((kt + 1) & 1) * KT_F,
                           sm + SM_V_OFF + ((kt + 1) & 1) * VT_F,
                           Kb, Vb, kt + 1, t);
        float* Ksm = sm + (kt & 1) * KT_F;
        float* Vsm = sm + SM_V_OFF + (kt & 1) * VT_F;

        // S = Q K^T (scale folded into Q)
        float s[8][4] = {};
#pragma unroll
        for (int ks = 0; ks < 8; ks++) {
            int kk = ks * 8 + tig;
#pragma unroll
            for (int nt = 0; nt < 8; nt++) {
                int n = nt * 8 + gid;
                uint32_t b0 = __float_as_uint(Ksm[n * KS_LD + kk]);
                uint32_t b1 = __float_as_uint(Ksm[n * KS_LD + kk + 4]);
                mma_tf32(s[nt], qa[ks][0], qa[ks][1], qa[ks][2], qa[ks][3], b0, b1);
            }
        }

        if (kt * 64 + 63 > qt * 128 + wrow) {
#pragma unroll
            for (int nt = 0; nt < 8; nt++) {
                int col = kt * 64 + nt * 8 + 2 * tig;
                if (col > r0g)     s[nt][0] = -INFINITY;
                if (col + 1 > r0g) s[nt][1] = -INFINITY;
                if (col > r1g)     s[nt][2] = -INFINITY;
                if (col + 1 > r1g) s[nt][3] = -INFINITY;
            }
        }

        float mt0 = -INFINITY, mt1 = -INFINITY;
#pragma unroll
        for (int nt = 0; nt < 8; nt++) {
            mt0 = fmaxf(mt0, fmaxf(s[nt][0], s[nt][1]));
            mt1 = fmaxf(mt1, fmaxf(s[nt][2], s[nt][3]));
        }
        mt0 = fmaxf(mt0, __shfl_xor_sync(0xffffffffu, mt0, 1));
        mt0 = fmaxf(mt0, __shfl_xor_sync(0xffffffffu, mt0, 2));
        mt1 = fmaxf(mt1, __shfl_xor_sync(0xffffffffu, mt1, 1));
        mt1 = fmaxf(mt1, __shfl_xor_sync(0xffffffffu, mt1, 2));

        float mn0 = fmaxf(m0, mt0), mn1 = fmaxf(m1, mt1);
        float al0 = __expf(m0 - mn0), al1 = __expf(m1 - mn1);
        m0 = mn0; m1 = mn1;

        float ls0 = 0.f, ls1 = 0.f;
#pragma unroll
        for (int nt = 0; nt < 8; nt++) {
            s[nt][0] = __expf(s[nt][0] - mn0);
            s[nt][1] = __expf(s[nt][1] - mn0);
            s[nt][2] = __expf(s[nt][2] - mn1);
            s[nt][3] = __expf(s[nt][3] - mn1);
            ls0 += s[nt][0] + s[nt][1];
            ls1 += s[nt][2] + s[nt][3];
        }
        ls0 += __shfl_xor_sync(0xffffffffu, ls0, 1);
        ls0 += __shfl_xor_sync(0xffffffffu, ls0, 2);
        ls1 += __shfl_xor_sync(0xffffffffu, ls1, 1);
        ls1 += __shfl_xor_sync(0xffffffffu, ls1, 2);
        l0 = l0 * al0 + ls0;
        l1 = l1 * al1 + ls1;

#pragma unroll
        for (int nt = 0; nt < 8; nt++) {
            o[nt][0] *= al0; o[nt][1] *= al0;
            o[nt][2] *= al1; o[nt][3] *= al1;
        }

        // stage P as tf32 patterns (convert once here)
#pragma unroll
        for (int nt = 0; nt < 8; nt++) {
            *(float2*)&pr0[nt * 8 + 2 * tig] =
                make_float2(__uint_as_float(f2tf(s[nt][0])), __uint_as_float(f2tf(s[nt][1])));
            *(float2*)&pr1[nt * 8 + 2 * tig] =
                make_float2(__uint_as_float(f2tf(s[nt][2])), __uint_as_float(f2tf(s[nt][3])));
        }
        __syncwarp();

        // O += P * V (pure LDS + mma)
#pragma unroll
        for (int ks = 0; ks < 8; ks++) {
            int kk = ks * 8;
            uint32_t pa0 = __float_as_uint(pr0[kk + tig]);
            uint32_t pa1 = __float_as_uint(pr1[kk + tig]);
            uint32_t pa2 = __float_as_uint(pr0[kk + tig + 4]);
            uint32_t pa3 = __float_as_uint(pr1[kk + tig + 4]);
#pragma unroll
            for (int nt = 0; nt < 8; nt++) {
                int d = nt * 8 + gid;
                uint32_t b0 = __float_as_uint(Vsm[(kk + tig) * VS_LD + d]);
                uint32_t b1 = __float_as_uint(Vsm[(kk + tig + 4) * VS_LD + d]);
                mma_tf32(o[nt], pa0, pa1, pa2, pa3, b0, b1);
            }
        }
        __syncwarp();
    }

    // finalize: divide by l, write tf32 pattern into Yt [B,T,C]
    float inv0 = 1.f / l0, inv1 = 1.f / l1;
    int b = bh >> 4, h = bh & 15;
    size_t off0 = ((size_t)b * T_SEQ + r0g) * C_EMB + h * 64;
    size_t off1 = ((size_t)b * T_SEQ + r1g) * C_EMB + h * 64;
#pragma unroll
    for (int nt = 0; nt < 8; nt++) {
        int col = nt * 8 + 2 * tig;
        *(float2*)&Yt[off0 + col] =
            make_float2(__uint_as_float(f2tf(o[nt][0] * inv0)),
                        __uint_as_float(f2tf(o[nt][1] * inv0)));
        *(float2*)&Yt[off1 + col] =
            make_float2(__uint_as_float(f2tf(o[nt][2] * inv1)),
                        __uint_as_float(f2tf(o[nt][3] * inv1)));
    }
}

// ---------------------------------------------------------------------------
extern "C" void kernel_launch(void* const* d_in, const int* in_sizes, int n_in,
                              void* d_out, int out_size) {
    const float* x      = (const float*)d_in[0];
    const float* w_qkv  = (const float*)d_in[1];
    const float* w_proj = (const float*)d_in[2];
    float* out = (float*)d_out;

    float *p_qkv, *p_xt, *p_wqt, *p_wpt, *p_q, *p_k, *p_v, *p_yt;
    cudaGetSymbolAddress((void**)&p_qkv, g_qkv);
    cudaGetSymbolAddress((void**)&p_xt, g_xt);
    cudaGetSymbolAddress((void**)&p_wqt, g_wqt);
    cudaGetSymbolAddress((void**)&p_wpt, g_wpt);
    cudaGetSymbolAddress((void**)&p_q, g_q);
    cudaGetSymbolAddress((void**)&p_k, g_k);
    cudaGetSymbolAddress((void**)&p_v, g_v);
    cudaGetSymbolAddress((void**)&p_yt, g_yt);

    // RoPE tables + tf32 pre-conversion
    rope_table_kernel<<<(T_SEQ * H_DIM + 255) / 256, 256>>>();
    cvt_kernel<<<(M_TOT * C_EMB / 4 + 255) / 256, 256>>>(
        (const float4*)x, (float4*)p_xt, M_TOT * C_EMB / 4);
    cvt_kernel<<<(3 * C_EMB * C_EMB / 4 + 255) / 256, 256>>>(
        (const float4*)w_qkv, (float4*)p_wqt, 3 * C_EMB * C_EMB / 4);
    cvt_kernel<<<(C_EMB * C_EMB / 4 + 255) / 256, 256>>>(
        (const float4*)w_proj, (float4*)p_wpt, C_EMB * C_EMB / 4);

    cudaFuncSetAttribute(sgemm_tf32,
                         cudaFuncAttributeMaxDynamicSharedMemorySize, GEMM_SMEM_BYTES);

    // QKV GEMM: [4096,1024] x [3072,1024]^T -> [4096,3072]
    sgemm_tf32<<<dim3((3 * C_EMB) / 128, M_TOT / 128), 256, GEMM_SMEM_BYTES>>>(
        p_xt, p_wqt, p_qkv, M_TOT, 3 * C_EMB, C_EMB);

    // RoPE + split into tf32 [B,H,T,D]
    rope_split_kernel<<<(B_SZ * T_SEQ * C_EMB) / 256, 256>>>();

    // Flash attention
    int smem_bytes = ATTN_SMEM_FLOATS * 4;
    cudaFuncSetAttribute(attn_mma_kernel,
                         cudaFuncAttributeMaxDynamicSharedMemorySize, smem_bytes);
    attn_mma_kernel<<<dim3(T_SEQ / 128, B_SZ * NHEAD), 256, smem_bytes>>>(
        p_q, p_k, p_v, p_yt);

    // Proj GEMM: [4096,1024] x [1024,1024]^T -> out
    sgemm_tf32<<<dim3(C_EMB / 128, M_TOT / 128), 256, GEMM_SMEM_BYTES>>>(
        p_yt, p_wpt, out, M_TOT, C_EMB, C_EMB);
}

// round 10
// speedup vs baseline: 1.7902x; 1.0131x over previous
#include <cuda_runtime.h>
#include <math.h>
#include <stdint.h>

#define B_SZ   2
#define T_SEQ  2048
#define C_EMB  1024
#define NHEAD  16
#define H_DIM  64
#define M_TOT  (B_SZ * T_SEQ)   // 4096

// Scratch (static device arrays)
__device__ float g_qkv[(size_t)M_TOT * 3 * C_EMB];           // [B,T,3C] fp32
__device__ float g_xt[(size_t)M_TOT * C_EMB];                // tf32 patterns
__device__ float g_wqt[(size_t)3 * C_EMB * C_EMB];
__device__ float g_wpt[(size_t)C_EMB * C_EMB];
__device__ float g_q[(size_t)B_SZ * NHEAD * T_SEQ * H_DIM];  // tf32 pattern, pre-scaled
__device__ float g_k[(size_t)B_SZ * NHEAD * T_SEQ * H_DIM];  // tf32 pattern
__device__ float g_v[(size_t)B_SZ * NHEAD * T_SEQ * H_DIM];  // tf32 pattern
__device__ float g_yt[(size_t)M_TOT * C_EMB];                // tf32 pattern
__device__ float g_cos[T_SEQ * H_DIM];
__device__ float g_sin[T_SEQ * H_DIM];

// ---------------------------------------------------------------------------
__device__ __forceinline__ uint32_t f2tf(float x) {
    uint32_t r;
    asm("cvt.rna.tf32.f32 %0, %1;" : "=r"(r) : "f"(x));
    return r;
}
__device__ __forceinline__ void mma_tf32(float* c,
                                         uint32_t a0, uint32_t a1, uint32_t a2, uint32_t a3,
                                         uint32_t b0, uint32_t b1) {
    asm volatile(
        "mma.sync.aligned.m16n8k8.row.col.f32.tf32.tf32.f32 "
        "{%0,%1,%2,%3}, {%4,%5,%6,%7}, {%8,%9}, {%0,%1,%2,%3};"
        : "+f"(c[0]), "+f"(c[1]), "+f"(c[2]), "+f"(c[3])
        : "r"(a0), "r"(a1), "r"(a2), "r"(a3), "r"(b0), "r"(b1));
}
__device__ __forceinline__ void cp16(uint32_t saddr, const void* g) {
    asm volatile("cp.async.cg.shared.global [%0], [%1], 16;" :: "r"(saddr), "l"(g));
}

// ---------------------------------------------------------------------------
// fp32 -> tf32 bit-pattern convert (vectorized)
// ---------------------------------------------------------------------------
__global__ void cvt_kernel(const float4* __restrict__ src,
                           float4* __restrict__ dst, int n4) {
    int i = blockIdx.x * blockDim.x + threadIdx.x;
    if (i >= n4) return;
    float4 v = src[i];
    v.x = __uint_as_float(f2tf(v.x));
    v.y = __uint_as_float(f2tf(v.y));
    v.z = __uint_as_float(f2tf(v.z));
    v.w = __uint_as_float(f2tf(v.w));
    dst[i] = v;
}

// ---------------------------------------------------------------------------
// RoPE table
// ---------------------------------------------------------------------------
__global__ void rope_table_kernel() {
    int i = blockIdx.x * blockDim.x + threadIdx.x;
    if (i >= T_SEQ * H_DIM) return;
    int t = i >> 6;
    int d = i & 63;
    double f = pow(10000.0, -(double)(d & 31) / 32.0);
    double ang = (double)t * f;
    g_cos[i] = (float)cos(ang);
    g_sin[i] = (float)sin(ang);
}

// ---------------------------------------------------------------------------
// Single-pass tf32 SGEMM: C[M,N] = A[M,K] * B[N,K]^T
// 128x128 tile, BK=16, 256 threads, warp tile 32x64, 3-stage cp.async.
// ---------------------------------------------------------------------------
#define ALD 20
#define TILE_F (128 * ALD)          // 2560
#define STAGE_F (2 * TILE_F)        // 5120
#define GEMM_SMEM_BYTES (3 * STAGE_F * 4)  // 61440

__device__ __forceinline__ void gemm_load_stage(
    float* sm, int s, const float* A, const float* B,
    int K, int bm, int bn, int k0, int t) {
    float* base = sm + s * STAGE_F;
#pragma unroll
    for (int c = 0; c < 2; c++) {
        int cc = t * 2 + c;
        int row = cc >> 2;
        int k4 = (cc & 3) * 4;
        uint32_t so = (uint32_t)__cvta_generic_to_shared(base + row * ALD + k4);
        cp16(so,              A + (size_t)(bm + row) * K + k0 + k4);
        cp16(so + TILE_F * 4, B + (size_t)(bn + row) * K + k0 + k4);
    }
    asm volatile("cp.async.commit_group;");
}

__global__ __launch_bounds__(256)
void sgemm_tf32(const float* __restrict__ A, const float* __restrict__ B,
                float* __restrict__ Cm, int M, int N, int K) {
    extern __shared__ __align__(16) float sm[];

    int t = threadIdx.x;
    int lane = t & 31, w = t >> 5;
    int gid = lane >> 2, tig = lane & 3;
    int mw = (w & 3) * 32;
    int nw = (w >> 2) * 64;
    int bm = blockIdx.y * 128, bn = blockIdx.x * 128;

    float c[2][8][4] = {};

    int nkt = K / 16;
    gemm_load_stage(sm, 0, A, B, K, bm, bn, 0, t);
    gemm_load_stage(sm, 1, A, B, K, bm, bn, 16, t);

    for (int kt = 0; kt < nkt; kt++) {
        asm volatile("cp.async.wait_group 1;");
        __syncthreads();
        if (kt + 2 < nkt)
            gemm_load_stage(sm, (kt + 2) % 3, A, B, K, bm, bn, (kt + 2) * 16, t);
        else
            asm volatile("cp.async.commit_group;");
        float* As = sm + (kt % 3) * STAGE_F;
        float* Bs = As + TILE_F;

#pragma unroll
        for (int ks = 0; ks < 2; ks++) {
            int kb = ks * 8;
            uint32_t ah[2][4];
#pragma unroll
            for (int mt = 0; mt < 2; mt++) {
                int row = mw + mt * 16 + gid;
                ah[mt][0] = __float_as_uint(As[row * ALD + kb + tig]);
                ah[mt][1] = __float_as_uint(As[(row + 8) * ALD + kb + tig]);
                ah[mt][2] = __float_as_uint(As[row * ALD + kb + tig + 4]);
                ah[mt][3] = __float_as_uint(As[(row + 8) * ALD + kb + tig + 4]);
            }
            uint32_t bh[8][2];
#pragma unroll
            for (int nt = 0; nt < 8; nt++) {
                int n = nw + nt * 8 + gid;
                bh[nt][0] = __float_as_uint(Bs[n * ALD + kb + tig]);
                bh[nt][1] = __float_as_uint(Bs[n * ALD + kb + tig + 4]);
            }
#pragma unroll
            for (int mt = 0; mt < 2; mt++)
#pragma unroll
                for (int nt = 0; nt < 8; nt++)
                    mma_tf32(c[mt][nt], ah[mt][0], ah[mt][1], ah[mt][2], ah[mt][3],
                             bh[nt][0], bh[nt][1]);
        }
    }

#pragma unroll
    for (int mt = 0; mt < 2; mt++) {
        int row = bm + mw + mt * 16 + gid;
#pragma unroll
        for (int nt = 0; nt < 8; nt++) {
            int col = bn + nw + nt * 8 + 2 * tig;
            *(float2*)&Cm[(size_t)row * N + col] =
                make_float2(c[mt][nt][0], c[mt][nt][1]);
            *(float2*)&Cm[(size_t)(row + 8) * N + col] =
                make_float2(c[mt][nt][2], c[mt][nt][3]);
        }
    }
}

// ---------------------------------------------------------------------------
// RoPE + split -> tf32-pattern q (pre-scaled by 1/8), k, v in [B,H,T,D]
// ---------------------------------------------------------------------------
__global__ void rope_split_kernel() {
    int i = blockIdx.x * blockDim.x + threadIdx.x;
    int d = i & 63;
    int h = (i >> 6) & 15;
    int t = (i >> 10) & 2047;
    int b = i >> 21;

    const float* base = g_qkv + (size_t)(b * T_SEQ + t) * (3 * C_EMB);
    float cs = g_cos[t * 64 + d];
    float sn = g_sin[t * 64 + d];

    int o  = h * 64 + d;
    int o2 = h * 64 + ((d < 32) ? (d + 32) : (d - 32));
    float sgn = (d < 32) ? -1.f : 1.f;

    float qv = base[o];
    float qp = base[o2];
    float kv = base[C_EMB + o];
    float kp = base[C_EMB + o2];

    size_t oi = ((size_t)(b * NHEAD + h) * T_SEQ + t) * H_DIM + d;
    g_q[oi] = __uint_as_float(f2tf((qv * cs + sgn * qp * sn) * 0.125f));
    g_k[oi] = __uint_as_float(f2tf(kv * cs + sgn * kp * sn));
    g_v[oi] = __uint_as_float(f2tf(base[2 * C_EMB + o]));
}

// ---------------------------------------------------------------------------
// Flash attention (causal), tf32 mma, cp.async double-buffered K/V.
// Block 256 threads (8 warps), 128 Q rows (16/warp), 64-key tiles.
// P never touches smem: S C-fragments are permuted into PV A-fragments
// with intra-quad shfl. Smem = 2*K + 2*V tiles = 70 KB -> 3 CTAs/SM.
// ---------------------------------------------------------------------------
#define KS_LD 68
#define VS_LD 72
#define KT_F (64 * KS_LD)                 // 4352
#define VT_F (64 * VS_LD)                 // 4608
#define SM_V_OFF (2 * KT_F)
#define ATTN_SMEM_FLOATS (SM_V_OFF + 2 * VT_F)   // 17920 floats = 71680 B

__device__ __forceinline__ void attn_load_tile(
    float* Ksm, float* Vsm, const float* Kb, const float* Vb, int kt, int t) {
    int row = t >> 2, dc = (t & 3) * 16;
    const float* kp = Kb + ((size_t)kt * 64 + row) * H_DIM + dc;
    const float* vp = Vb + ((size_t)kt * 64 + row) * H_DIM + dc;
    uint32_t ks = (uint32_t)__cvta_generic_to_shared(Ksm + row * KS_LD + dc);
    uint32_t vs = (uint32_t)__cvta_generic_to_shared(Vsm + row * VS_LD + dc);
#pragma unroll
    for (int j = 0; j < 4; j++) {
        cp16(ks + j * 16, kp + j * 4);
        cp16(vs + j * 16, vp + j * 4);
    }
    asm volatile("cp.async.commit_group;");
}

__global__ __launch_bounds__(256)
void attn_mma_kernel(const float* __restrict__ Q, const float* __restrict__ Kg,
                     const float* __restrict__ Vg, float* __restrict__ Yt) {
    extern __shared__ __align__(16) float sm[];

    int t = threadIdx.x;
    int lane = t & 31, w = t >> 5;
    int gid = lane >> 2, tig = lane & 3;
    int qt = blockIdx.x;
    int bh = blockIdx.y;
    int wrow = w * 16;

    const float* Qb = Q  + (size_t)bh * T_SEQ * H_DIM;
    const float* Kb = Kg + (size_t)bh * T_SEQ * H_DIM;
    const float* Vb = Vg + (size_t)bh * T_SEQ * H_DIM;

    int r0g = qt * 128 + wrow + gid;
    int r1g = r0g + 8;
    uint32_t qa[8][4];
    {
        const float* qp0 = Qb + (size_t)r0g * H_DIM;
        const float* qp1 = Qb + (size_t)r1g * H_DIM;
#pragma unroll
        for (int ks = 0; ks < 8; ks++) {
            int kk = ks * 8 + tig;
            qa[ks][0] = __float_as_uint(qp0[kk]);
            qa[ks][1] = __float_as_uint(qp1[kk]);
            qa[ks][2] = __float_as_uint(qp0[kk + 4]);
            qa[ks][3] = __float_as_uint(qp1[kk + 4]);
        }
    }

    float o[8][4] = {};
    float m0 = -INFINITY, m1 = -INFINITY;
    float l0 = 0.f, l1 = 0.f;

    // shfl sources for C-frag -> A-frag permutation (intra-quad)
    int srcA = (lane & ~3) | (tig >> 1);   // cols tig
    int srcB = srcA + 2;                   // cols tig+4
    bool oddc = (tig & 1);

    int ktmax = 2 * qt + 1;
    attn_load_tile(sm, sm + SM_V_OFF, Kb, Vb, 0, t);

    for (int kt = 0; kt <= ktmax; kt++) {
        asm volatile("cp.async.wait_group 0;");
        __syncthreads();
        if (kt + 1 <= ktmax)
            attn_load_tile(sm + ((kt + 1) & 1) * KT_F,
                           sm + SM_V_OFF + ((kt + 1) & 1) * VT_F,
                           Kb, Vb, kt + 1, t);
        float* Ksm = sm + (kt & 1) * KT_F;
        float* Vsm = sm + SM_V_OFF + (kt & 1) * VT_F;

        // S = Q K^T (scale folded into Q)
        float s[8][4] = {};
#pragma unroll
        for (int ks = 0; ks < 8; ks++) {
            int kk = ks * 8 + tig;
#pragma unroll
            for (int nt = 0; nt < 8; nt++) {
                int n = nt * 8 + gid;
                uint32_t b0 = __float_as_uint(Ksm[n * KS_LD + kk]);
                uint32_t b1 = __float_as_uint(Ksm[n * KS_LD + kk + 4]);
                mma_tf32(s[nt], qa[ks][0], qa[ks][1], qa[ks][2], qa[ks][3], b0, b1);
            }
        }

        if (kt * 64 + 63 > qt * 128 + wrow) {
#pragma unroll
            for (int nt = 0; nt < 8; nt++) {
                int col = kt * 64 + nt * 8 + 2 * tig;
                if (col > r0g)     s[nt][0] = -INFINITY;
                if (col + 1 > r0g) s[nt][1] = -INFINITY;
                if (col > r1g)     s[nt][2] = -INFINITY;
                if (col + 1 > r1g) s[nt][3] = -INFINITY;
            }
        }

        float mt0 = -INFINITY, mt1 = -INFINITY;
#pragma unroll
        for (int nt = 0; nt < 8; nt++) {
            mt0 = fmaxf(mt0, fmaxf(s[nt][0], s[nt][1]));
            mt1 = fmaxf(mt1, fmaxf(s[nt][2], s[nt][3]));
        }
        mt0 = fmaxf(mt0, __shfl_xor_sync(0xffffffffu, mt0, 1));
        mt0 = fmaxf(mt0, __shfl_xor_sync(0xffffffffu, mt0, 2));
        mt1 = fmaxf(mt1, __shfl_xor_sync(0xffffffffu, mt1, 1));
        mt1 = fmaxf(mt1, __shfl_xor_sync(0xffffffffu, mt1, 2));

        float mn0 = fmaxf(m0, mt0), mn1 = fmaxf(m1, mt1);
        float al0 = __expf(m0 - mn0), al1 = __expf(m1 - mn1);
        m0 = mn0; m1 = mn1;

        float ls0 = 0.f, ls1 = 0.f;
#pragma unroll
        for (int nt = 0; nt < 8; nt++) {
            s[nt][0] = __expf(s[nt][0] - mn0);
            s[nt][1] = __expf(s[nt][1] - mn0);
            s[nt][2] = __expf(s[nt][2] - mn1);
            s[nt][3] = __expf(s[nt][3] - mn1);
            ls0 += s[nt][0] + s[nt][1];
            ls1 += s[nt][2] + s[nt][3];
        }
        ls0 += __shfl_xor_sync(0xffffffffu, ls0, 1);
        ls0 += __shfl_xor_sync(0xffffffffu, ls0, 2);
        ls1 += __shfl_xor_sync(0xffffffffu, ls1, 1);
        ls1 += __shfl_xor_sync(0xffffffffu, ls1, 2);
        l0 = l0 * al0 + ls0;
        l1 = l1 * al1 + ls1;

#pragma unroll
        for (int nt = 0; nt < 8; nt++) {
            o[nt][0] *= al0; o[nt][1] *= al0;
            o[nt][2] *= al1; o[nt][3] *= al1;
        }

        // O += P * V ; P fragments built by intra-quad shfl permutation.
        // C-frag (rows gid/gid+8, cols 2tig/2tig+1) -> A-frag (cols tig, tig+4).
#pragma unroll
        for (int ks = 0; ks < 8; ks++) {
            float c0 = __uint_as_float(f2tf(s[ks][0]));
            float c1 = __uint_as_float(f2tf(s[ks][1]));
            float c2 = __uint_as_float(f2tf(s[ks][2]));
            float c3 = __uint_as_float(f2tf(s[ks][3]));
            float a00 = __shfl_sync(0xffffffffu, c0, srcA);
            float a01 = __shfl_sync(0xffffffffu, c1, srcA);
            float a10 = __shfl_sync(0xffffffffu, c2, srcA);
            float a11 = __shfl_sync(0xffffffffu, c3, srcA);
            float b00 = __shfl_sync(0xffffffffu, c0, srcB);
            float b01 = __shfl_sync(0xffffffffu, c1, srcB);
            float b10 = __shfl_sync(0xffffffffu, c2, srcB);
            float b11 = __shfl_sync(0xffffffffu, c3, srcB);
            uint32_t pa0 = __float_as_uint(oddc ? a01 : a00);  // (r0, tig)
            uint32_t pa1 = __float_as_uint(oddc ? a11 : a10);  // (r1, tig)
            uint32_t pa2 = __float_as_uint(oddc ? b01 : b00);  // (r0, tig+4)
            uint32_t pa3 = __float_as_uint(oddc ? b11 : b10);  // (r1, tig+4)
            int kk = ks * 8;
#pragma unroll
            for (int nt = 0; nt < 8; nt++) {
                int d = nt * 8 + gid;
                uint32_t b0 = __float_as_uint(Vsm[(kk + tig) * VS_LD + d]);
                uint32_t b1 = __float_as_uint(Vsm[(kk + tig + 4) * VS_LD + d]);
                mma_tf32(o[nt], pa0, pa1, pa2, pa3, b0, b1);
            }
        }
    }

    // finalize: divide by l, write tf32 pattern into Yt [B,T,C]
    float inv0 = 1.f / l0, inv1 = 1.f / l1;
    int b = bh >> 4, h = bh & 15;
    size_t off0 = ((size_t)b * T_SEQ + r0g) * C_EMB + h * 64;
    size_t off1 = ((size_t)b * T_SEQ + r1g) * C_EMB + h * 64;
#pragma unroll
    for (int nt = 0; nt < 8; nt++) {
        int col = nt * 8 + 2 * tig;
        *(float2*)&Yt[off0 + col] =
            make_float2(__uint_as_float(f2tf(o[nt][0] * inv0)),
                        __uint_as_float(f2tf(o[nt][1] * inv0)));
        *(float2*)&Yt[off1 + col] =
            make_float2(__uint_as_float(f2tf(o[nt][2] * inv1)),
                        __uint_as_float(f2tf(o[nt][3] * inv1)));
    }
}

// ---------------------------------------------------------------------------
extern "C" void kernel_launch(void* const* d_in, const int* in_sizes, int n_in,
                              void* d_out, int out_size) {
    const float* x      = (const float*)d_in[0];
    const float* w_qkv  = (const float*)d_in[1];
    const float* w_proj = (const float*)d_in[2];
    float* out = (float*)d_out;

    float *p_qkv, *p_xt, *p_wqt, *p_wpt, *p_q, *p_k, *p_v, *p_yt;
    cudaGetSymbolAddress((void**)&p_qkv, g_qkv);
    cudaGetSymbolAddress((void**)&p_xt, g_xt);
    cudaGetSymbolAddress((void**)&p_wqt, g_wqt);
    cudaGetSymbolAddress((void**)&p_wpt, g_wpt);
    cudaGetSymbolAddress((void**)&p_q, g_q);
    cudaGetSymbolAddress((void**)&p_k, g_k);
    cudaGetSymbolAddress((void**)&p_v, g_v);
    cudaGetSymbolAddress((void**)&p_yt, g_yt);

    // RoPE tables + tf32 pre-conversion
    rope_table_kernel<<<(T_SEQ * H_DIM + 255) / 256, 256>>>();
    cvt_kernel<<<(M_TOT * C_EMB / 4 + 255) / 256, 256>>>(
        (const float4*)x, (float4*)p_xt, M_TOT * C_EMB / 4);
    cvt_kernel<<<(3 * C_EMB * C_EMB / 4 + 255) / 256, 256>>>(
        (const float4*)w_qkv, (float4*)p_wqt, 3 * C_EMB * C_EMB / 4);
    cvt_kernel<<<(C_EMB * C_EMB / 4 + 255) / 256, 256>>>(
        (const float4*)w_proj, (float4*)p_wpt, C_EMB * C_EMB / 4);

    cudaFuncSetAttribute(sgemm_tf32,
                         cudaFuncAttributeMaxDynamicSharedMemorySize, GEMM_SMEM_BYTES);

    // QKV GEMM: [4096,1024] x [3072,1024]^T -> [4096,3072]
    sgemm_tf32<<<dim3((3 * C_EMB) / 128, M_TOT / 128), 256, GEMM_SMEM_BYTES>>>(
        p_xt, p_wqt, p_qkv, M_TOT, 3 * C_EMB, C_EMB);

    // RoPE + split into tf32 [B,H,T,D]
    rope_split_kernel<<<(B_SZ * T_SEQ * C_EMB) / 256, 256>>>();

    // Flash attention
    int smem_bytes = ATTN_SMEM_FLOATS * 4;   // 71680
    cudaFuncSetAttribute(attn_mma_kernel,
                         cudaFuncAttributeMaxDynamicSharedMemorySize, smem_bytes);
    attn_mma_kernel<<<dim3(T_SEQ / 128, B_SZ * NHEAD), 256, smem_bytes>>>(
        p_q, p_k, p_v, p_yt);

    // Proj GEMM: [4096,1024] x [1024,1024]^T -> out
    sgemm_tf32<<<dim3(C_EMB / 128, M_TOT / 128), 256, GEMM_SMEM_BYTES>>>(
        p_yt, p_wpt, out, M_TOT, C_EMB, C_EMB);
}